// round 13
// baseline (speedup 1.0000x reference)
#include <cuda_runtime.h>
#include <cuda_bf16.h>
#include <math.h>
#include <stdint.h>

#define H_ 8
#define DIM_ 256
#define INNER_ 512
#define B_ 4
#define NPTS 32768
#define BH_ (B_*H_)
#define PSPLITS 32
#define LDA 40    // mma_gemm smem row stride
#define LDTA 136  // pgemm A trans-tile row stride
#define LDTB 72   // pgemm B trans-tile row stride

using bf16 = __nv_bfloat16;

__device__ bf16 g_xHi[(size_t)B_ * NPTS * DIM_];
__device__ bf16 g_xLo[(size_t)B_ * NPTS * DIM_];
__device__ bf16 g_swHi[(size_t)B_ * NPTS * INNER_];
__device__ bf16 g_swLo[(size_t)B_ * NPTS * INNER_];
__device__ bf16 g_WcombHi[INNER_ * DIM_];
__device__ bf16 g_WcombLo[INNER_ * DIM_];
__device__ float g_lbias[INNER_];
__device__ float g_Ppart[(size_t)B_ * PSPLITS * INNER_ * DIM_];
__device__ float g_psn[(size_t)B_ * PSPLITS * INNER_];
__device__ float g_st[(size_t)BH_ * 4096];
__device__ float g_kn[(size_t)B_ * 4096];
__device__ float g_v[(size_t)B_ * 4096];
__device__ float g_M[(size_t)B_ * DIM_ * INNER_];
__device__ bf16 g_MHi[(size_t)B_ * DIM_ * INNER_];
__device__ bf16 g_MLo[(size_t)B_ * DIM_ * INNER_];

__device__ __forceinline__ void split1(float v, bf16& h, bf16& l) {
    h = __float2bfloat16(v);
    l = __float2bfloat16(v - __bfloat162float(h));
}
__device__ __forceinline__ uint32_t sptr(const void* p) {
    return (uint32_t)__cvta_generic_to_shared(p);
}
__device__ __forceinline__ void ldsm4(uint32_t* r, uint32_t a) {
    asm volatile("ldmatrix.sync.aligned.m8n8.x4.shared.b16 {%0,%1,%2,%3}, [%4];"
                 : "=r"(r[0]), "=r"(r[1]), "=r"(r[2]), "=r"(r[3]) : "r"(a));
}
__device__ __forceinline__ void ldsm4t(uint32_t* r, uint32_t a) {
    asm volatile("ldmatrix.sync.aligned.m8n8.x4.trans.shared.b16 {%0,%1,%2,%3}, [%4];"
                 : "=r"(r[0]), "=r"(r[1]), "=r"(r[2]), "=r"(r[3]) : "r"(a));
}
__device__ __forceinline__ void mma16816(float* d, const uint32_t* a, const uint32_t* b) {
    asm volatile("mma.sync.aligned.m16n8k16.row.col.f32.bf16.bf16.f32 "
                 "{%0,%1,%2,%3}, {%4,%5,%6,%7}, {%8,%9}, {%0,%1,%2,%3};"
                 : "+f"(d[0]), "+f"(d[1]), "+f"(d[2]), "+f"(d[3])
                 : "r"(a[0]), "r"(a[1]), "r"(a[2]), "r"(a[3]), "r"(b[0]), "r"(b[1]));
}
__device__ __forceinline__ void cp16(bf16* s, const bf16* g) {
    asm volatile("cp.async.cg.shared.global [%0], [%1], 16;" :: "r"(sptr(s)), "l"(g));
}
__device__ __forceinline__ void cp_commit() { asm volatile("cp.async.commit_group;"); }
template<int NN> __device__ __forceinline__ void cp_wait() {
    asm volatile("cp.async.wait_group %0;" :: "n"(NN));
}

__global__ __launch_bounds__(256) void splitX_k(const float* __restrict__ x) {
    long i = (long)blockIdx.x * 256 + threadIdx.x;
    float4 v = reinterpret_cast<const float4*>(x)[i];
    bf16 h0,l0,h1,l1,h2,l2,h3,l3;
    split1(v.x,h0,l0); split1(v.y,h1,l1); split1(v.z,h2,l2); split1(v.w,h3,l3);
    __nv_bfloat162 a(h0,h1), b(h2,h3), c(l0,l1), d(l2,l3);
    reinterpret_cast<uint2*>(g_xHi)[i] = make_uint2(*(uint32_t*)&a, *(uint32_t*)&b);
    reinterpret_cast<uint2*>(g_xLo)[i] = make_uint2(*(uint32_t*)&c, *(uint32_t*)&d);
}

__global__ __launch_bounds__(256) void prep_k(
    const float* __restrict__ Wx, const float* __restrict__ Wslice,
    const float* __restrict__ bx, const float* __restrict__ bslice) {
    int idx = blockIdx.x * 256 + threadIdx.x;
    int n = idx >> 8, k = idx & 255, h = n >> 6, g = n & 63;
    float s = 0.f;
    #pragma unroll 16
    for (int d = 0; d < 64; d++) s += Wslice[g*64+d] * Wx[(h*64+d)*DIM_ + k];
    split1(s, g_WcombHi[idx], g_WcombLo[idx]);
    if (k == 0) {
        float sb = 0.f;
        for (int d = 0; d < 64; d++) sb += Wslice[g*64+d] * bx[h*64+d];
        g_lbias[n] = sb + bslice[g];
    }
}

// ---- HMMA GEMM (R11-proven): 128x128 tile, warps 2(M)x4(N), 64 acc regs ----
template<bool SOFTMAX, bool OUT_PAIR>
__global__ __launch_bounds__(256) void mma_gemm(
    const bf16* __restrict__ Ahi, const bf16* __restrict__ Alo,
    const bf16* __restrict__ Bhi, const bf16* __restrict__ Blo,
    const float* __restrict__ bias, const float* __restrict__ temp,
    float* __restrict__ C, bf16* __restrict__ Chi, bf16* __restrict__ Clo,
    int N, int K, long sA, long sB, long sC)
{
    extern __shared__ bf16 smem[];
    __shared__ float red[2][4][128];
    const int STG = 128 * LDA;

    const int tid = threadIdx.x, lane = tid & 31, wid = tid >> 5;
    const int warpM = wid & 1, warpN = wid >> 1;
    const long rowBase = (long)blockIdx.x * 128;
    const int colBase = blockIdx.y * 128;

    Ahi += (long)blockIdx.z * sA; Alo += (long)blockIdx.z * sA;
    Bhi += (long)blockIdx.z * sB; Blo += (long)blockIdx.z * sB;
    if (OUT_PAIR) { Chi += (long)blockIdx.z * sC; Clo += (long)blockIdx.z * sC; }
    else          { C += (long)blockIdx.z * sC; }

    float acc[4][4][4] = {};
    const int NK = K / 32;

    auto load = [&](int st, int kt) {
        bf16* s = smem + st * 4 * STG;
        const long ko = (long)kt * 32;
        #pragma unroll
        for (int l = 0; l < 2; l++) {
            int f = l * 256 + tid, r = f >> 2, c8 = (f & 3) * 8;
            cp16(s + r*LDA + c8,         Ahi + (rowBase + r) * K + ko + c8);
            cp16(s + STG + r*LDA + c8,   Alo + (rowBase + r) * K + ko + c8);
            cp16(s + 2*STG + r*LDA + c8, Bhi + (long)(colBase + r) * K + ko + c8);
            cp16(s + 3*STG + r*LDA + c8, Blo + (long)(colBase + r) * K + ko + c8);
        }
    };

    load(0, 0); cp_commit();
    for (int kt = 0; kt < NK; kt++) {
        if (kt + 1 < NK) { load((kt + 1) & 1, kt + 1); cp_commit(); cp_wait<1>(); }
        else             { cp_wait<0>(); }
        __syncthreads();
        const bf16* s = smem + (kt & 1) * 4 * STG;
        #pragma unroll
        for (int kh = 0; kh < 2; kh++) {
            uint32_t ah[4][4], al[4][4], bh[4][2], bl[4][2];
            #pragma unroll
            for (int mi = 0; mi < 4; mi++) {
                int rrow = warpM*64 + mi*16 + (lane & 15);
                int ccol = kh*16 + ((lane >> 4) << 3);
                ldsm4(ah[mi], sptr(s + rrow*LDA + ccol));
                ldsm4(al[mi], sptr(s + STG + rrow*LDA + ccol));
            }
            #pragma unroll
            for (int p = 0; p < 2; p++) {
                int nrow = warpN*32 + p*16 + ((lane & 7) | (((lane >> 4) & 1) << 3));
                int ccol = kh*16 + (((lane >> 3) & 1) << 3);
                uint32_t t[4];
                ldsm4(t, sptr(s + 2*STG + nrow*LDA + ccol));
                bh[2*p][0]=t[0]; bh[2*p][1]=t[1]; bh[2*p+1][0]=t[2]; bh[2*p+1][1]=t[3];
                ldsm4(t, sptr(s + 3*STG + nrow*LDA + ccol));
                bl[2*p][0]=t[0]; bl[2*p][1]=t[1]; bl[2*p+1][0]=t[2]; bl[2*p+1][1]=t[3];
            }
            #pragma unroll
            for (int mi = 0; mi < 4; mi++)
                #pragma unroll
                for (int ni = 0; ni < 4; ni++) {
                    mma16816(acc[mi][ni], ah[mi], bh[ni]);
                    mma16816(acc[mi][ni], ah[mi], bl[ni]);
                    mma16816(acc[mi][ni], al[mi], bh[ni]);
                }
        }
        __syncthreads();
    }

    float bc0[4], bc1[4];
    #pragma unroll
    for (int ni = 0; ni < 4; ni++) {
        int col = colBase + warpN*32 + ni*8 + (lane & 3)*2;
        bc0[ni] = bias[col]; bc1[ni] = bias[col + 1];
    }

    if (SOFTMAX) {
        const float invt = 1.0f / temp[blockIdx.y * 2 + (warpN >> 1)];
        #pragma unroll
        for (int mi = 0; mi < 4; mi++)
            #pragma unroll
            for (int ni = 0; ni < 4; ni++) {
                acc[mi][ni][0] = (acc[mi][ni][0] + bc0[ni]) * invt;
                acc[mi][ni][1] = (acc[mi][ni][1] + bc1[ni]) * invt;
                acc[mi][ni][2] = (acc[mi][ni][2] + bc0[ni]) * invt;
                acc[mi][ni][3] = (acc[mi][ni][3] + bc1[ni]) * invt;
            }
        #pragma unroll
        for (int mi = 0; mi < 4; mi++)
            #pragma unroll
            for (int rh = 0; rh < 2; rh++) {
                float m = -1e30f;
                #pragma unroll
                for (int ni = 0; ni < 4; ni++) {
                    m = fmaxf(m, acc[mi][ni][rh*2]);
                    m = fmaxf(m, acc[mi][ni][rh*2+1]);
                }
                m = fmaxf(m, __shfl_xor_sync(0xffffffffu, m, 1));
                m = fmaxf(m, __shfl_xor_sync(0xffffffffu, m, 2));
                red[0][warpN][warpM*64 + mi*16 + rh*8 + (lane >> 2)] = m;
            }
        __syncthreads();
        const int wb = warpN & 2;
        #pragma unroll
        for (int mi = 0; mi < 4; mi++)
            #pragma unroll
            for (int rh = 0; rh < 2; rh++) {
                int row = warpM*64 + mi*16 + rh*8 + (lane >> 2);
                float M2 = fmaxf(red[0][wb][row], red[0][wb + 1][row]);
                float ssum = 0.f;
                #pragma unroll
                for (int ni = 0; ni < 4; ni++) {
                    float e0 = __expf(acc[mi][ni][rh*2] - M2);
                    float e1 = __expf(acc[mi][ni][rh*2+1] - M2);
                    acc[mi][ni][rh*2] = e0; acc[mi][ni][rh*2+1] = e1;
                    ssum += e0 + e1;
                }
                ssum += __shfl_xor_sync(0xffffffffu, ssum, 1);
                ssum += __shfl_xor_sync(0xffffffffu, ssum, 2);
                red[1][warpN][row] = ssum;
            }
        __syncthreads();
        #pragma unroll
        for (int mi = 0; mi < 4; mi++)
            #pragma unroll
            for (int rh = 0; rh < 2; rh++) {
                int rloc = warpM*64 + mi*16 + rh*8 + (lane >> 2);
                long row = rowBase + rloc;
                float inv = 1.0f / (red[1][wb][rloc] + red[1][wb + 1][rloc]);
                #pragma unroll
                for (int ni = 0; ni < 4; ni++) {
                    int col = colBase + warpN*32 + ni*8 + (lane & 3)*2;
                    float v0 = acc[mi][ni][rh*2] * inv;
                    float v1 = acc[mi][ni][rh*2+1] * inv;
                    bf16 h0, l0, h1, l1;
                    split1(v0, h0, l0); split1(v1, h1, l1);
                    *reinterpret_cast<__nv_bfloat162*>(Chi + row*N + col) = __nv_bfloat162(h0, h1);
                    *reinterpret_cast<__nv_bfloat162*>(Clo + row*N + col) = __nv_bfloat162(l0, l1);
                }
            }
    } else {
        #pragma unroll
        for (int mi = 0; mi < 4; mi++)
            #pragma unroll
            for (int ni = 0; ni < 4; ni++) {
                int col = colBase + warpN*32 + ni*8 + (lane & 3)*2;
                #pragma unroll
                for (int rh = 0; rh < 2; rh++) {
                    long row = rowBase + warpM*64 + mi*16 + rh*8 + (lane >> 2);
                    float v0 = acc[mi][ni][rh*2] + bc0[ni];
                    float v1 = acc[mi][ni][rh*2+1] + bc1[ni];
                    if (OUT_PAIR) {
                        bf16 h0, l0, h1, l1;
                        split1(v0, h0, l0); split1(v1, h1, l1);
                        *reinterpret_cast<__nv_bfloat162*>(Chi + row*N + col) = __nv_bfloat162(h0, h1);
                        *reinterpret_cast<__nv_bfloat162*>(Clo + row*N + col) = __nv_bfloat162(l0, l1);
                    } else {
                        *reinterpret_cast<float2*>(C + row*N + col) = make_float2(v0, v1);
                    }
                }
            }
    }
}

// ---- P GEMM (split-K=32, HMMA, 3-stage): P[b][inner][dim] = sw[b]^T @ X[b] ----
__global__ __launch_bounds__(256) void pgemm_k()
{
    extern __shared__ bf16 smem[];
    constexpr int APL = 32 * LDTA;
    constexpr int BPL = 32 * LDTB;
    constexpr int STAGE = 2 * APL + 2 * BPL;   // 13312 elems

    const int tid = threadIdx.x, lane = tid & 31, wid = tid >> 5;
    const int warpM = wid & 3, warpN = wid >> 2;
    const int mBase = blockIdx.x * 128, nBase = blockIdx.y * 64;
    const int z = blockIdx.z, b = z >> 5, sp = z & 31;
    const long nStart = (long)b * NPTS + sp * (NPTS / PSPLITS);
    const bool doSN = (warpN == 0) && (blockIdx.y == 0);

    float acc[2][4][4] = {};
    float accS[2][4] = {};
    uint32_t bones[2] = {0x3F803F80u, 0x3F803F80u};

    auto load = [&](int st, int it) {
        bf16* s = smem + st * STAGE;
        const long g0 = nStart + it * 32;
        #pragma unroll
        for (int l = 0; l < 4; l++) {
            int f = l * 256 + tid;
            int pl = f >> 9;
            int r = (f >> 4) & 31, c = (f & 15) * 8;
            const bf16* g = (pl ? g_swLo : g_swHi) + (g0 + r) * INNER_ + mBase + c;
            cp16(s + pl * APL + r * LDTA + c, g);
        }
        #pragma unroll
        for (int l = 0; l < 2; l++) {
            int f = l * 256 + tid;
            int pl = f >> 8;
            int r = (f >> 3) & 31, c = (f & 7) * 8;
            const bf16* g = (pl ? g_xLo : g_xHi) + (g0 + r) * DIM_ + nBase + c;
            cp16(s + 2 * APL + pl * BPL + r * LDTB + c, g);
        }
    };

    const int NIT = (NPTS / PSPLITS) / 32;     // 32
    load(0, 0); cp_commit();
    load(1, 1); cp_commit();
    int st2 = 2;                               // slot for the it+2 load
    for (int it = 0; it < NIT; it++) {
        if (it + 2 < NIT) { load(st2, it + 2); cp_commit(); cp_wait<2>(); }
        else if (it + 1 < NIT) { cp_wait<1>(); }
        else { cp_wait<0>(); }
        __syncthreads();
        const int cur = st2 + 1 >= 3 ? st2 + 1 - 3 : st2 + 1;   // == it%3
        if (++st2 == 3) st2 = 0;
        const bf16* s = smem + cur * STAGE;
        const bf16* sB = s + 2 * APL;
        #pragma unroll
        for (int kh = 0; kh < 2; kh++) {
            const int g = lane >> 3, l8 = lane & 7;
            uint32_t ah[2][4], al[2][4], bh[4][2], bl[4][2];
            int kA = kh*16 + ((g >> 1) << 3) + l8, mA = (g & 1) << 3;
            #pragma unroll
            for (int mi = 0; mi < 2; mi++) {
                int mrow = warpM*32 + mi*16 + mA;
                ldsm4t(ah[mi], sptr(s + kA*LDTA + mrow));
                ldsm4t(al[mi], sptr(s + APL + kA*LDTA + mrow));
            }
            int kB = kh*16 + ((g & 1) << 3) + l8, nB0 = (g >> 1) << 3;
            #pragma unroll
            for (int p = 0; p < 2; p++) {
                int ncol = warpN*32 + p*16 + nB0;
                uint32_t t[4];
                ldsm4t(t, sptr(sB + kB*LDTB + ncol));
                bh[2*p][0]=t[0]; bh[2*p][1]=t[1]; bh[2*p+1][0]=t[2]; bh[2*p+1][1]=t[3];
                ldsm4t(t, sptr(sB + BPL + kB*LDTB + ncol));
                bl[2*p][0]=t[0]; bl[2*p][1]=t[1]; bl[2*p+1][0]=t[2]; bl[2*p+1][1]=t[3];
            }
            if (doSN) {
                #pragma unroll
                for (int mi = 0; mi < 2; mi++) {
                    mma16816(accS[mi], ah[mi], bones);
                    mma16816(accS[mi], al[mi], bones);
                }
            }
            #pragma unroll
            for (int mi = 0; mi < 2; mi++)
                #pragma unroll
                for (int ni = 0; ni < 4; ni++) {
                    mma16816(acc[mi][ni], ah[mi], bh[ni]);
                    mma16816(acc[mi][ni], ah[mi], bl[ni]);
                    mma16816(acc[mi][ni], al[mi], bh[ni]);
                }
        }
        __syncthreads();
    }

    float* P = g_Ppart + (long)z * INNER_ * DIM_;
    #pragma unroll
    for (int mi = 0; mi < 2; mi++)
        #pragma unroll
        for (int ni = 0; ni < 4; ni++) {
            int col = nBase + warpN*32 + ni*8 + (lane & 3)*2;
            #pragma unroll
            for (int rh = 0; rh < 2; rh++) {
                int row = mBase + warpM*32 + mi*16 + rh*8 + (lane >> 2);
                *reinterpret_cast<float2*>(P + (long)row * DIM_ + col) =
                    make_float2(acc[mi][ni][rh*2], acc[mi][ni][rh*2+1]);
            }
        }
    if (doSN && (lane & 3) == 0) {
        #pragma unroll
        for (int mi = 0; mi < 2; mi++) {
            int r0 = mBase + warpM*32 + mi*16 + (lane >> 2);
            g_psn[(long)z * INNER_ + r0]     = accS[mi][0];
            g_psn[(long)z * INNER_ + r0 + 8] = accS[mi][2];
        }
    }
}

__global__ __launch_bounds__(256) void st_k(
    const float* __restrict__ Wfx, const float* __restrict__ bfx)
{
    extern __shared__ float Ps[];
    __shared__ float inv_sn[64], sn_s[64];
    const int bh = blockIdx.x, b = bh >> 3, h = bh & 7;
    const int tid = threadIdx.x;
    for (int e = tid; e < 64 * 256; e += 256) {
        int g = e >> 8, c = e & 255;
        float s = 0.f;
        #pragma unroll 8
        for (int sp = 0; sp < PSPLITS; sp++)
            s += g_Ppart[((long)(b*PSPLITS + sp) * INNER_ + h*64 + g) * DIM_ + c];
        Ps[g*257 + c] = s;
    }
    if (tid < 64) {
        float s = 0.f;
        #pragma unroll 8
        for (int sp = 0; sp < PSPLITS; sp++)
            s += g_psn[(long)(b*PSPLITS + sp) * INNER_ + h*64 + tid];
        sn_s[tid] = s;
        inv_sn[tid] = 1.0f / (s + 1e-5f);
    }
    __syncthreads();
    const int d = tid & 63, q = tid >> 6;
    const float bfxd = bfx[h*64 + d];
    const float* wrow = Wfx + (long)(h*64 + d) * DIM_;
    float acc[16] = {};
    for (int c = 0; c < 256; c++) {
        float w = wrow[c];
        #pragma unroll
        for (int i = 0; i < 16; i++) acc[i] += Ps[(q*16 + i)*257 + c] * w;
    }
    #pragma unroll
    for (int i = 0; i < 16; i++) {
        int g = q*16 + i;
        g_st[(long)bh * 4096 + g*64 + d] = (acc[i] + sn_s[g] * bfxd) * inv_sn[g];
    }
}

__global__ __launch_bounds__(256) void kv_k(
    const float* __restrict__ Wk, const float* __restrict__ Wv)
{
    __shared__ float kv[4096], kb[4096], rn[64];
    const int b = blockIdx.x, tid = threadIdx.x;
    for (int e = tid; e < 4096; e += 256) {
        float s = 0.f;
        #pragma unroll
        for (int h = 0; h < 8; h++) s += g_st[(long)(b*8 + h) * 4096 + e];
        kv[e] = s * 0.125f;
    }
    __syncthreads();
    {
        const int d = tid & 63;
        const float4* wkp = reinterpret_cast<const float4*>(Wk + d*64);
        const float4* wvp = reinterpret_cast<const float4*>(Wv + d*64);
        #pragma unroll
        for (int k = 0; k < 16; k++) {
            int g = (tid >> 6) + k*4;
            const float4* kvp = reinterpret_cast<const float4*>(kv + g*64);
            float sk = 0.f, sv = 0.f;
            #pragma unroll
            for (int e4 = 0; e4 < 16; e4++) {
                float4 x = kvp[e4], w1 = wkp[e4], w2 = wvp[e4];
                sk += x.x*w1.x + x.y*w1.y + x.z*w1.z + x.w*w1.w;
                sv += x.x*w2.x + x.y*w2.y + x.z*w2.z + x.w*w2.w;
            }
            kb[g*64 + d] = sk;
            g_v[(long)b * 4096 + g*64 + d] = sv;
        }
    }
    __syncthreads();
    if (tid < 64) {
        float s = 0.f;
        for (int d = 0; d < 64; d++) { float x = kb[tid*64 + d]; s += x*x; }
        rn[tid] = 1.0f / fmaxf(sqrtf(s), 1e-12f);
    }
    __syncthreads();
    for (int e = tid; e < 4096; e += 256)
        g_kn[(long)b * 4096 + e] = kb[e] * rn[e >> 6];
}

__global__ __launch_bounds__(256) void attn_k(
    const float* __restrict__ Wq, const float* __restrict__ Wout,
    const float* __restrict__ attn_scale, const float* __restrict__ res_scale)
{
    extern __shared__ float sm[];
    float* sst = sm;
    float* sq  = sm + 4096;
    float* sc  = sm + 8192;
    const int bh = blockIdx.x, b = bh >> 3, h = bh & 7;
    const int tid = threadIdx.x;

    for (int e = tid; e < 4096; e += 256) sst[e] = g_st[(long)bh * 4096 + e];
    __syncthreads();
    {
        const int d = tid & 63;
        const float4* wp = reinterpret_cast<const float4*>(Wq + d*64);
        #pragma unroll
        for (int k = 0; k < 16; k++) {
            int g = (tid >> 6) + k*4;
            const float4* sp = reinterpret_cast<const float4*>(sst + g*64);
            float s = 0.f;
            #pragma unroll
            for (int e4 = 0; e4 < 16; e4++) {
                float4 w = wp[e4], x = sp[e4];
                s += w.x*x.x + w.y*x.y + w.z*x.z + w.w*x.w;
            }
            sq[g*64 + d] = s;
        }
    }
    __syncthreads();
    if (tid < 64) {
        float s = 0.f;
        for (int d = 0; d < 64; d++) { float x = sq[tid*64 + d]; s += x*x; }
        float inv = 1.0f / fmaxf(sqrtf(s), 1e-12f);
        for (int d = 0; d < 64; d++) sq[tid*64 + d] *= inv;
    }
    __syncthreads();
    {
        const float asc = attn_scale[h];
        const int ss = tid & 63;
        const float4* kp = reinterpret_cast<const float4*>(g_kn + (long)b * 4096 + ss*64);
        #pragma unroll
        for (int k = 0; k < 16; k++) {
            int g = (tid >> 6) + k*4;
            const float4* qp = reinterpret_cast<const float4*>(sq + g*64);
            float s = 0.f;
            #pragma unroll
            for (int d4 = 0; d4 < 16; d4++) {
                float4 kk = kp[d4], qq = qp[d4];
                s += kk.x*qq.x + kk.y*qq.y + kk.z*qq.z + kk.w*qq.w;
            }
            sc[g*65 + ss] = s * asc;
        }
    }
    __syncthreads();
    if (tid < 64) {
        float m = -1e30f;
        for (int s = 0; s < 64; s++) m = fmaxf(m, sc[tid*65 + s]);
        float sum = 0.f;
        for (int s = 0; s < 64; s++) {
            float e = __expf(sc[tid*65 + s] - m);
            sc[tid*65 + s] = e; sum += e;
        }
        float inv = 1.0f / sum;
        for (int s = 0; s < 64; s++) sc[tid*65 + s] *= inv;
    }
    for (int e = tid; e < 4096; e += 256) sq[e] = g_v[(long)b * 4096 + e];
    __syncthreads();

    const float res = *res_scale;
    float outreg[16];
    {
        const int d = tid & 63;
        #pragma unroll
        for (int k = 0; k < 16; k++) {
            int g = (tid >> 6) + k*4;
            float s = 0.f;
            #pragma unroll 16
            for (int ss = 0; ss < 64; ss++) s += sc[g*65 + ss] * sq[ss*64 + d];
            outreg[k] = s + res * sst[g*64 + d];
        }
    }
    __syncthreads();
    {
        const int d = tid & 63;
        #pragma unroll
        for (int k = 0; k < 16; k++) sst[((tid >> 6) + k*4)*64 + d] = outreg[k];
    }
    __syncthreads();
    {
        const int c = tid;
        const float4* wp = reinterpret_cast<const float4*>(Wout + c*INNER_ + h*64);
        for (int g = 0; g < 64; g++) {
            const float4* op = reinterpret_cast<const float4*>(sst + g*64);
            float s = 0.f;
            #pragma unroll
            for (int d4 = 0; d4 < 16; d4++) {
                float4 w = wp[d4], o = op[d4];
                s += w.x*o.x + w.y*o.y + w.z*o.z + w.w*o.w;
            }
            g_M[((long)b * DIM_ + c) * INNER_ + h*64 + g] = s;
        }
    }
}

__global__ __launch_bounds__(256) void splitM_k() {
    int i = blockIdx.x * 256 + threadIdx.x;
    split1(g_M[i], g_MHi[i], g_MLo[i]);
}

extern "C" void kernel_launch(void* const* d_in, const int* in_sizes, int n_in,
                              void* d_out, int out_size)
{
    const float* x         = (const float*)d_in[0];
    const float* Wfx       = (const float*)d_in[1];
    const float* bfx       = (const float*)d_in[2];
    const float* Wx        = (const float*)d_in[3];
    const float* bx        = (const float*)d_in[4];
    const float* Wslice    = (const float*)d_in[5];
    const float* bslice    = (const float*)d_in[6];
    const float* temp      = (const float*)d_in[7];
    const float* Wq        = (const float*)d_in[8];
    const float* Wk        = (const float*)d_in[9];
    const float* Wv        = (const float*)d_in[10];
    const float* res_scale = (const float*)d_in[11];
    const float* attn_scl  = (const float*)d_in[12];
    const float* Wout      = (const float*)d_in[13];
    const float* bout      = (const float*)d_in[14];
    float* out = (float*)d_out;

    bf16 *p_xHi, *p_xLo, *p_swHi, *p_swLo, *p_WcHi, *p_WcLo, *p_MHi, *p_MLo;
    float *p_lbias;
    cudaGetSymbolAddress((void**)&p_xHi, g_xHi);
    cudaGetSymbolAddress((void**)&p_xLo, g_xLo);
    cudaGetSymbolAddress((void**)&p_swHi, g_swHi);
    cudaGetSymbolAddress((void**)&p_swLo, g_swLo);
    cudaGetSymbolAddress((void**)&p_WcHi, g_WcombHi);
    cudaGetSymbolAddress((void**)&p_WcLo, g_WcombLo);
    cudaGetSymbolAddress((void**)&p_MHi, g_MHi);
    cudaGetSymbolAddress((void**)&p_MLo, g_MLo);
    cudaGetSymbolAddress((void**)&p_lbias, g_lbias);

    const int GEMM_SMEM = 2 * 4 * 128 * LDA * (int)sizeof(bf16);            // 81920
    const int P_SMEM    = 3 * (2*32*LDTA + 2*32*LDTB) * (int)sizeof(bf16);  // 79872
    const int ST_SMEM   = 64 * 257 * (int)sizeof(float);
    cudaFuncSetAttribute(mma_gemm<true, true>,  cudaFuncAttributeMaxDynamicSharedMemorySize, GEMM_SMEM);
    cudaFuncSetAttribute(mma_gemm<false, false>, cudaFuncAttributeMaxDynamicSharedMemorySize, GEMM_SMEM);
    cudaFuncSetAttribute(pgemm_k, cudaFuncAttributeMaxDynamicSharedMemorySize, P_SMEM);
    cudaFuncSetAttribute(st_k, cudaFuncAttributeMaxDynamicSharedMemorySize, ST_SMEM);
    cudaFuncSetAttribute(attn_k, cudaFuncAttributeMaxDynamicSharedMemorySize, 49408);

    splitX_k<<<(B_ * NPTS * DIM_) / 4 / 256, 256>>>(x);
    prep_k<<<512, 256>>>(Wx, Wslice, bx, bslice);

    // sw = softmax_G((x @ Wcomb^T + lbias)/temp) -> bf16 hi/lo planes
    mma_gemm<true, true><<<dim3(1024, 4, 1), 256, GEMM_SMEM>>>(
        p_xHi, p_xLo, p_WcHi, p_WcLo, p_lbias, temp,
        nullptr, p_swHi, p_swLo, INNER_, DIM_, 0, 0, 0);

    // P[b] = sw[b]^T @ X[b] (split-K=32, 3-stage; grid 2048 -> ~6.9 waves)
    pgemm_k<<<dim3(4, 4, B_ * PSPLITS), 256, P_SMEM>>>();

    st_k<<<BH_, 256, ST_SMEM>>>(Wfx, bfx);
    kv_k<<<B_, 256>>>(Wk, Wv);
    attn_k<<<BH_, 256, 49408>>>(Wq, Wout, attn_scl, res_scale);
    splitM_k<<<2048, 256>>>();

    // out = sw @ M[b]^T + bout
    mma_gemm<false, false><<<dim3(256, 2, B_), 256, GEMM_SMEM>>>(
        p_swHi, p_swLo, p_MHi, p_MLo, bout, nullptr,
        out, nullptr, nullptr, DIM_, INNER_,
        (long)NPTS * INNER_, (long)DIM_ * INNER_, (long)NPTS * DIM_);
}

// round 16
// speedup vs baseline: 1.1489x; 1.1489x over previous
#include <cuda_runtime.h>
#include <cuda_bf16.h>
#include <math.h>
#include <stdint.h>

#define H_ 8
#define DIM_ 256
#define INNER_ 512
#define B_ 4
#define NPTS 32768
#define BH_ (B_*H_)
#define PSPLITS 16
#define LDA 40    // mma_gemm smem row stride
#define LDTA 136  // pgemm A trans-tile row stride
#define LDTB 72   // pgemm B trans-tile row stride

using bf16 = __nv_bfloat16;

__device__ bf16 g_xHi[(size_t)B_ * NPTS * DIM_];
__device__ bf16 g_xLo[(size_t)B_ * NPTS * DIM_];
__device__ bf16 g_swHi[(size_t)B_ * NPTS * INNER_];
__device__ bf16 g_swLo[(size_t)B_ * NPTS * INNER_];
__device__ bf16 g_WcombHi[INNER_ * DIM_];
__device__ bf16 g_WcombLo[INNER_ * DIM_];
__device__ float g_lbias[INNER_];
__device__ float g_Ppart[(size_t)B_ * PSPLITS * INNER_ * DIM_];
__device__ float g_psn[(size_t)B_ * PSPLITS * INNER_];
__device__ float g_st[(size_t)BH_ * 4096];
__device__ float g_kn[(size_t)B_ * 4096];
__device__ float g_v[(size_t)B_ * 4096];
__device__ bf16 g_MHi[(size_t)B_ * DIM_ * INNER_];
__device__ bf16 g_MLo[(size_t)B_ * DIM_ * INNER_];

__device__ __forceinline__ void split1(float v, bf16& h, bf16& l) {
    h = __float2bfloat16(v);
    l = __float2bfloat16(v - __bfloat162float(h));
}
__device__ __forceinline__ uint32_t sptr(const void* p) {
    return (uint32_t)__cvta_generic_to_shared(p);
}
__device__ __forceinline__ void ldsm4(uint32_t* r, uint32_t a) {
    asm volatile("ldmatrix.sync.aligned.m8n8.x4.shared.b16 {%0,%1,%2,%3}, [%4];"
                 : "=r"(r[0]), "=r"(r[1]), "=r"(r[2]), "=r"(r[3]) : "r"(a));
}
__device__ __forceinline__ void ldsm4t(uint32_t* r, uint32_t a) {
    asm volatile("ldmatrix.sync.aligned.m8n8.x4.trans.shared.b16 {%0,%1,%2,%3}, [%4];"
                 : "=r"(r[0]), "=r"(r[1]), "=r"(r[2]), "=r"(r[3]) : "r"(a));
}
__device__ __forceinline__ void mma16816(float* d, const uint32_t* a, const uint32_t* b) {
    asm volatile("mma.sync.aligned.m16n8k16.row.col.f32.bf16.bf16.f32 "
                 "{%0,%1,%2,%3}, {%4,%5,%6,%7}, {%8,%9}, {%0,%1,%2,%3};"
                 : "+f"(d[0]), "+f"(d[1]), "+f"(d[2]), "+f"(d[3])
                 : "r"(a[0]), "r"(a[1]), "r"(a[2]), "r"(a[3]), "r"(b[0]), "r"(b[1]));
}
__device__ __forceinline__ void cp16(bf16* s, const bf16* g) {
    asm volatile("cp.async.cg.shared.global [%0], [%1], 16;" :: "r"(sptr(s)), "l"(g));
}
__device__ __forceinline__ void cp_commit() { asm volatile("cp.async.commit_group;"); }
template<int NN> __device__ __forceinline__ void cp_wait() {
    asm volatile("cp.async.wait_group %0;" :: "n"(NN));
}

__global__ __launch_bounds__(256) void splitX_k(const float* __restrict__ x) {
    long i = (long)blockIdx.x * 256 + threadIdx.x;
    float4 v = reinterpret_cast<const float4*>(x)[i];
    bf16 h0,l0,h1,l1,h2,l2,h3,l3;
    split1(v.x,h0,l0); split1(v.y,h1,l1); split1(v.z,h2,l2); split1(v.w,h3,l3);
    __nv_bfloat162 a(h0,h1), b(h2,h3), c(l0,l1), d(l2,l3);
    reinterpret_cast<uint2*>(g_xHi)[i] = make_uint2(*(uint32_t*)&a, *(uint32_t*)&b);
    reinterpret_cast<uint2*>(g_xLo)[i] = make_uint2(*(uint32_t*)&c, *(uint32_t*)&d);
}

__global__ __launch_bounds__(256) void prep_k(
    const float* __restrict__ Wx, const float* __restrict__ Wslice,
    const float* __restrict__ bx, const float* __restrict__ bslice) {
    int idx = blockIdx.x * 256 + threadIdx.x;
    int n = idx >> 8, k = idx & 255, h = n >> 6, g = n & 63;
    float s = 0.f;
    #pragma unroll 16
    for (int d = 0; d < 64; d++) s += Wslice[g*64+d] * Wx[(h*64+d)*DIM_ + k];
    split1(s, g_WcombHi[idx], g_WcombLo[idx]);
    if (k == 0) {
        float sb = 0.f;
        for (int d = 0; d < 64; d++) sb += Wslice[g*64+d] * bx[h*64+d];
        g_lbias[n] = sb + bslice[g];
    }
}

// ---- HMMA GEMM: 128x128 tile, warps 2(M)x4(N); B-frags first + per-mi A
// loads to cut live registers; capped at 128 regs for 2 blocks/SM. ----
template<bool SOFTMAX, bool OUT_PAIR>
__global__ __launch_bounds__(256, 2) void mma_gemm(
    const bf16* __restrict__ Ahi, const bf16* __restrict__ Alo,
    const bf16* __restrict__ Bhi, const bf16* __restrict__ Blo,
    const float* __restrict__ bias, const float* __restrict__ temp,
    float* __restrict__ C, bf16* __restrict__ Chi, bf16* __restrict__ Clo,
    int N, int K, long sA, long sB, long sC)
{
    extern __shared__ bf16 smem[];
    __shared__ float red[2][4][128];
    const int STG = 128 * LDA;

    const int tid = threadIdx.x, lane = tid & 31, wid = tid >> 5;
    const int warpM = wid & 1, warpN = wid >> 1;
    const long rowBase = (long)blockIdx.x * 128;
    const int colBase = blockIdx.y * 128;

    Ahi += (long)blockIdx.z * sA; Alo += (long)blockIdx.z * sA;
    Bhi += (long)blockIdx.z * sB; Blo += (long)blockIdx.z * sB;
    if (OUT_PAIR) { Chi += (long)blockIdx.z * sC; Clo += (long)blockIdx.z * sC; }
    else          { C += (long)blockIdx.z * sC; }

    float acc[4][4][4] = {};
    const int NK = K / 32;

    auto load = [&](int st, int kt) {
        bf16* s = smem + st * 4 * STG;
        const long ko = (long)kt * 32;
        #pragma unroll
        for (int l = 0; l < 2; l++) {
            int f = l * 256 + tid, r = f >> 2, c8 = (f & 3) * 8;
            cp16(s + r*LDA + c8,         Ahi + (rowBase + r) * K + ko + c8);
            cp16(s + STG + r*LDA + c8,   Alo + (rowBase + r) * K + ko + c8);
            cp16(s + 2*STG + r*LDA + c8, Bhi + (long)(colBase + r) * K + ko + c8);
            cp16(s + 3*STG + r*LDA + c8, Blo + (long)(colBase + r) * K + ko + c8);
        }
    };

    load(0, 0); cp_commit();
    for (int kt = 0; kt < NK; kt++) {
        if (kt + 1 < NK) { load((kt + 1) & 1, kt + 1); cp_commit(); cp_wait<1>(); }
        else             { cp_wait<0>(); }
        __syncthreads();
        const bf16* s = smem + (kt & 1) * 4 * STG;
        #pragma unroll
        for (int kh = 0; kh < 2; kh++) {
            uint32_t bh[4][2], bl[4][2];
            #pragma unroll
            for (int p = 0; p < 2; p++) {
                int nrow = warpN*32 + p*16 + ((lane & 7) | (((lane >> 4) & 1) << 3));
                int ccol = kh*16 + (((lane >> 3) & 1) << 3);
                uint32_t t[4];
                ldsm4(t, sptr(s + 2*STG + nrow*LDA + ccol));
                bh[2*p][0]=t[0]; bh[2*p][1]=t[1]; bh[2*p+1][0]=t[2]; bh[2*p+1][1]=t[3];
                ldsm4(t, sptr(s + 3*STG + nrow*LDA + ccol));
                bl[2*p][0]=t[0]; bl[2*p][1]=t[1]; bl[2*p+1][0]=t[2]; bl[2*p+1][1]=t[3];
            }
            #pragma unroll
            for (int mi = 0; mi < 4; mi++) {
                uint32_t ah[4], al[4];
                int rrow = warpM*64 + mi*16 + (lane & 15);
                int ccol = kh*16 + ((lane >> 4) << 3);
                ldsm4(ah, sptr(s + rrow*LDA + ccol));
                ldsm4(al, sptr(s + STG + rrow*LDA + ccol));
                #pragma unroll
                for (int ni = 0; ni < 4; ni++) {
                    mma16816(acc[mi][ni], ah, bh[ni]);
                    mma16816(acc[mi][ni], ah, bl[ni]);
                    mma16816(acc[mi][ni], al, bh[ni]);
                }
            }
        }
        __syncthreads();
    }

    float bc0[4], bc1[4];
    #pragma unroll
    for (int ni = 0; ni < 4; ni++) {
        int col = colBase + warpN*32 + ni*8 + (lane & 3)*2;
        bc0[ni] = bias[col]; bc1[ni] = bias[col + 1];
    }

    if (SOFTMAX) {
        const float invt = 1.0f / temp[blockIdx.y * 2 + (warpN >> 1)];
        #pragma unroll
        for (int mi = 0; mi < 4; mi++)
            #pragma unroll
            for (int ni = 0; ni < 4; ni++) {
                acc[mi][ni][0] = (acc[mi][ni][0] + bc0[ni]) * invt;
                acc[mi][ni][1] = (acc[mi][ni][1] + bc1[ni]) * invt;
                acc[mi][ni][2] = (acc[mi][ni][2] + bc0[ni]) * invt;
                acc[mi][ni][3] = (acc[mi][ni][3] + bc1[ni]) * invt;
            }
        #pragma unroll
        for (int mi = 0; mi < 4; mi++)
            #pragma unroll
            for (int rh = 0; rh < 2; rh++) {
                float m = -1e30f;
                #pragma unroll
                for (int ni = 0; ni < 4; ni++) {
                    m = fmaxf(m, acc[mi][ni][rh*2]);
                    m = fmaxf(m, acc[mi][ni][rh*2+1]);
                }
                m = fmaxf(m, __shfl_xor_sync(0xffffffffu, m, 1));
                m = fmaxf(m, __shfl_xor_sync(0xffffffffu, m, 2));
                red[0][warpN][warpM*64 + mi*16 + rh*8 + (lane >> 2)] = m;
            }
        __syncthreads();
        const int wb = warpN & 2;
        #pragma unroll
        for (int mi = 0; mi < 4; mi++)
            #pragma unroll
            for (int rh = 0; rh < 2; rh++) {
                int row = warpM*64 + mi*16 + rh*8 + (lane >> 2);
                float M2 = fmaxf(red[0][wb][row], red[0][wb + 1][row]);
                float ssum = 0.f;
                #pragma unroll
                for (int ni = 0; ni < 4; ni++) {
                    float e0 = __expf(acc[mi][ni][rh*2] - M2);
                    float e1 = __expf(acc[mi][ni][rh*2+1] - M2);
                    acc[mi][ni][rh*2] = e0; acc[mi][ni][rh*2+1] = e1;
                    ssum += e0 + e1;
                }
                ssum += __shfl_xor_sync(0xffffffffu, ssum, 1);
                ssum += __shfl_xor_sync(0xffffffffu, ssum, 2);
                red[1][warpN][row] = ssum;
            }
        __syncthreads();
        #pragma unroll
        for (int mi = 0; mi < 4; mi++)
            #pragma unroll
            for (int rh = 0; rh < 2; rh++) {
                int rloc = warpM*64 + mi*16 + rh*8 + (lane >> 2);
                long row = rowBase + rloc;
                float inv = 1.0f / (red[1][wb][rloc] + red[1][wb + 1][rloc]);
                #pragma unroll
                for (int ni = 0; ni < 4; ni++) {
                    int col = colBase + warpN*32 + ni*8 + (lane & 3)*2;
                    float v0 = acc[mi][ni][rh*2] * inv;
                    float v1 = acc[mi][ni][rh*2+1] * inv;
                    bf16 h0, l0, h1, l1;
                    split1(v0, h0, l0); split1(v1, h1, l1);
                    *reinterpret_cast<__nv_bfloat162*>(Chi + row*N + col) = __nv_bfloat162(h0, h1);
                    *reinterpret_cast<__nv_bfloat162*>(Clo + row*N + col) = __nv_bfloat162(l0, l1);
                }
            }
    } else {
        #pragma unroll
        for (int mi = 0; mi < 4; mi++)
            #pragma unroll
            for (int ni = 0; ni < 4; ni++) {
                int col = colBase + warpN*32 + ni*8 + (lane & 3)*2;
                #pragma unroll
                for (int rh = 0; rh < 2; rh++) {
                    long row = rowBase + warpM*64 + mi*16 + rh*8 + (lane >> 2);
                    float v0 = acc[mi][ni][rh*2] + bc0[ni];
                    float v1 = acc[mi][ni][rh*2+1] + bc1[ni];
                    if (OUT_PAIR) {
                        bf16 h0, l0, h1, l1;
                        split1(v0, h0, l0); split1(v1, h1, l1);
                        *reinterpret_cast<__nv_bfloat162*>(Chi + row*N + col) = __nv_bfloat162(h0, h1);
                        *reinterpret_cast<__nv_bfloat162*>(Clo + row*N + col) = __nv_bfloat162(l0, l1);
                    } else {
                        *reinterpret_cast<float2*>(C + row*N + col) = make_float2(v0, v1);
                    }
                }
            }
    }
}

// ---- P GEMM (split-K=16, HMMA, R11-proven): P[b][inner][dim] = sw^T @ X ----
__global__ __launch_bounds__(256) void pgemm_k()
{
    extern __shared__ bf16 smem[];
    constexpr int APL = 32 * LDTA;
    constexpr int BPL = 32 * LDTB;
    constexpr int STAGE = 2 * APL + 2 * BPL;

    const int tid = threadIdx.x, lane = tid & 31, wid = tid >> 5;
    const int warpM = wid & 3, warpN = wid >> 2;
    const int mBase = blockIdx.x * 128, nBase = blockIdx.y * 64;
    const int z = blockIdx.z, b = z >> 4, sp = z & 15;
    const long nStart = (long)b * NPTS + sp * (NPTS / PSPLITS);
    const bool doSN = (warpN == 0) && (blockIdx.y == 0);

    float acc[2][4][4] = {};
    float accS[2][4] = {};
    uint32_t bones[2] = {0x3F803F80u, 0x3F803F80u};

    auto load = [&](int st, int it) {
        bf16* s = smem + st * STAGE;
        const long g0 = nStart + it * 32;
        #pragma unroll
        for (int l = 0; l < 4; l++) {
            int f = l * 256 + tid;
            int pl = f >> 9;
            int r = (f >> 4) & 31, c = (f & 15) * 8;
            const bf16* g = (pl ? g_swLo : g_swHi) + (g0 + r) * INNER_ + mBase + c;
            cp16(s + pl * APL + r * LDTA + c, g);
        }
        #pragma unroll
        for (int l = 0; l < 2; l++) {
            int f = l * 256 + tid;
            int pl = f >> 8;
            int r = (f >> 3) & 31, c = (f & 7) * 8;
            const bf16* g = (pl ? g_xLo : g_xHi) + (g0 + r) * DIM_ + nBase + c;
            cp16(s + 2 * APL + pl * BPL + r * LDTB + c, g);
        }
    };

    const int NIT = (NPTS / PSPLITS) / 32;
    load(0, 0); cp_commit();
    for (int it = 0; it < NIT; it++) {
        if (it + 1 < NIT) { load((it + 1) & 1, it + 1); cp_commit(); cp_wait<1>(); }
        else              { cp_wait<0>(); }
        __syncthreads();
        const bf16* s = smem + (it & 1) * STAGE;
        const bf16* sB = s + 2 * APL;
        #pragma unroll
        for (int kh = 0; kh < 2; kh++) {
            const int g = lane >> 3, l8 = lane & 7;
            uint32_t ah[2][4], al[2][4], bh[4][2], bl[4][2];
            int kA = kh*16 + ((g >> 1) << 3) + l8, mA = (g & 1) << 3;
            #pragma unroll
            for (int mi = 0; mi < 2; mi++) {
                int mrow = warpM*32 + mi*16 + mA;
                ldsm4t(ah[mi], sptr(s + kA*LDTA + mrow));
                ldsm4t(al[mi], sptr(s + APL + kA*LDTA + mrow));
            }
            int kB = kh*16 + ((g & 1) << 3) + l8, nB0 = (g >> 1) << 3;
            #pragma unroll
            for (int p = 0; p < 2; p++) {
                int ncol = warpN*32 + p*16 + nB0;
                uint32_t t[4];
                ldsm4t(t, sptr(sB + kB*LDTB + ncol));
                bh[2*p][0]=t[0]; bh[2*p][1]=t[1]; bh[2*p+1][0]=t[2]; bh[2*p+1][1]=t[3];
                ldsm4t(t, sptr(sB + BPL + kB*LDTB + ncol));
                bl[2*p][0]=t[0]; bl[2*p][1]=t[1]; bl[2*p+1][0]=t[2]; bl[2*p+1][1]=t[3];
            }
            if (doSN) {
                #pragma unroll
                for (int mi = 0; mi < 2; mi++) {
                    mma16816(accS[mi], ah[mi], bones);
                    mma16816(accS[mi], al[mi], bones);
                }
            }
            #pragma unroll
            for (int mi = 0; mi < 2; mi++)
                #pragma unroll
                for (int ni = 0; ni < 4; ni++) {
                    mma16816(acc[mi][ni], ah[mi], bh[ni]);
                    mma16816(acc[mi][ni], ah[mi], bl[ni]);
                    mma16816(acc[mi][ni], al[mi], bh[ni]);
                }
        }
        __syncthreads();
    }

    float* P = g_Ppart + (long)z * INNER_ * DIM_;
    #pragma unroll
    for (int mi = 0; mi < 2; mi++)
        #pragma unroll
        for (int ni = 0; ni < 4; ni++) {
            int col = nBase + warpN*32 + ni*8 + (lane & 3)*2;
            #pragma unroll
            for (int rh = 0; rh < 2; rh++) {
                int row = mBase + warpM*32 + mi*16 + rh*8 + (lane >> 2);
                *reinterpret_cast<float2*>(P + (long)row * DIM_ + col) =
                    make_float2(acc[mi][ni][rh*2], acc[mi][ni][rh*2+1]);
            }
        }
    if (doSN && (lane & 3) == 0) {
        #pragma unroll
        for (int mi = 0; mi < 2; mi++) {
            int r0 = mBase + warpM*32 + mi*16 + (lane >> 2);
            g_psn[(long)z * INNER_ + r0]     = accS[mi][0];
            g_psn[(long)z * INNER_ + r0 + 8] = accS[mi][2];
        }
    }
}

// ---- st_k: grid (BH_, 4); each block reduces 16 g's + does the Wfx fold ----
__global__ __launch_bounds__(256) void st_k(
    const float* __restrict__ Wfx, const float* __restrict__ bfx)
{
    __shared__ float Ps[16][257];
    __shared__ float inv_sn[16], sn_s[16];
    const int bh = blockIdx.x, gc = blockIdx.y;
    const int b = bh >> 3, h = bh & 7;
    const int tid = threadIdx.x;
    const int gBase = gc * 16;

    for (int e = tid; e < 16 * 256; e += 256) {
        int g = e >> 8, c = e & 255;
        float s = 0.f;
        #pragma unroll
        for (int sp = 0; sp < PSPLITS; sp++)
            s += g_Ppart[((long)(b*PSPLITS + sp) * INNER_ + h*64 + gBase + g) * DIM_ + c];
        Ps[g][c] = s;
    }
    if (tid < 16) {
        float s = 0.f;
        #pragma unroll
        for (int sp = 0; sp < PSPLITS; sp++)
            s += g_psn[(long)(b*PSPLITS + sp) * INNER_ + h*64 + gBase + tid];
        sn_s[tid] = s;
        inv_sn[tid] = 1.0f / (s + 1e-5f);
    }
    __syncthreads();
    const int d = tid & 63, q = tid >> 6;
    const float bfxd = bfx[h*64 + d];
    const float* wrow = Wfx + (long)(h*64 + d) * DIM_;
    float acc[4] = {};
    for (int c = 0; c < 256; c++) {
        float w = wrow[c];
        #pragma unroll
        for (int i = 0; i < 4; i++) acc[i] += Ps[q*4 + i][c] * w;
    }
    #pragma unroll
    for (int i = 0; i < 4; i++) {
        int g = q*4 + i;
        g_st[(long)bh * 4096 + (gBase + g)*64 + d] =
            (acc[i] + sn_s[g] * bfxd) * inv_sn[g];
    }
}

__global__ __launch_bounds__(256) void kv_k(
    const float* __restrict__ Wk, const float* __restrict__ Wv)
{
    __shared__ float kv[4096], kb[4096], rn[64];
    const int b = blockIdx.x, tid = threadIdx.x;
    for (int e = tid; e < 4096; e += 256) {
        float s = 0.f;
        #pragma unroll
        for (int h = 0; h < 8; h++) s += g_st[(long)(b*8 + h) * 4096 + e];
        kv[e] = s * 0.125f;
    }
    __syncthreads();
    {
        const int d = tid & 63;
        const float4* wkp = reinterpret_cast<const float4*>(Wk + d*64);
        const float4* wvp = reinterpret_cast<const float4*>(Wv + d*64);
        #pragma unroll
        for (int k = 0; k < 16; k++) {
            int g = (tid >> 6) + k*4;
            const float4* kvp = reinterpret_cast<const float4*>(kv + g*64);
            float sk = 0.f, sv = 0.f;
            #pragma unroll
            for (int e4 = 0; e4 < 16; e4++) {
                float4 x = kvp[e4], w1 = wkp[e4], w2 = wvp[e4];
                sk += x.x*w1.x + x.y*w1.y + x.z*w1.z + x.w*w1.w;
                sv += x.x*w2.x + x.y*w2.y + x.z*w2.z + x.w*w2.w;
            }
            kb[g*64 + d] = sk;
            g_v[(long)b * 4096 + g*64 + d] = sv;
        }
    }
    __syncthreads();
    if (tid < 64) {
        float s = 0.f;
        for (int d = 0; d < 64; d++) { float x = kb[tid*64 + d]; s += x*x; }
        rn[tid] = 1.0f / fmaxf(sqrtf(s), 1e-12f);
    }
    __syncthreads();
    for (int e = tid; e < 4096; e += 256)
        g_kn[(long)b * 4096 + e] = kb[e] * rn[e >> 6];
}

__global__ __launch_bounds__(256) void attn_k(
    const float* __restrict__ Wq, const float* __restrict__ Wout,
    const float* __restrict__ attn_scale, const float* __restrict__ res_scale)
{
    extern __shared__ float sm[];
    float* sst = sm;
    float* sq  = sm + 4096;
    float* sc  = sm + 8192;
    const int bh = blockIdx.x, b = bh >> 3, h = bh & 7;
    const int tid = threadIdx.x;

    for (int e = tid; e < 4096; e += 256) sst[e] = g_st[(long)bh * 4096 + e];
    __syncthreads();
    {
        const int d = tid & 63;
        const float4* wp = reinterpret_cast<const float4*>(Wq + d*64);
        #pragma unroll
        for (int k = 0; k < 16; k++) {
            int g = (tid >> 6) + k*4;
            const float4* sp = reinterpret_cast<const float4*>(sst + g*64);
            float s = 0.f;
            #pragma unroll
            for (int e4 = 0; e4 < 16; e4++) {
                float4 w = wp[e4], x = sp[e4];
                s += w.x*x.x + w.y*x.y + w.z*x.z + w.w*x.w;
            }
            sq[g*64 + d] = s;
        }
    }
    __syncthreads();
    if (tid < 64) {
        float s = 0.f;
        for (int d = 0; d < 64; d++) { float x = sq[tid*64 + d]; s += x*x; }
        float inv = 1.0f / fmaxf(sqrtf(s), 1e-12f);
        for (int d = 0; d < 64; d++) sq[tid*64 + d] *= inv;
    }
    __syncthreads();
    {
        const float asc = attn_scale[h];
        const int ss = tid & 63;
        const float4* kp = reinterpret_cast<const float4*>(g_kn + (long)b * 4096 + ss*64);
        #pragma unroll
        for (int k = 0; k < 16; k++) {
            int g = (tid >> 6) + k*4;
            const float4* qp = reinterpret_cast<const float4*>(sq + g*64);
            float s = 0.f;
            #pragma unroll
            for (int d4 = 0; d4 < 16; d4++) {
                float4 kk = kp[d4], qq = qp[d4];
                s += kk.x*qq.x + kk.y*qq.y + kk.z*qq.z + kk.w*qq.w;
            }
            sc[g*65 + ss] = s * asc;
        }
    }
    __syncthreads();
    if (tid < 64) {
        float m = -1e30f;
        for (int s = 0; s < 64; s++) m = fmaxf(m, sc[tid*65 + s]);
        float sum = 0.f;
        for (int s = 0; s < 64; s++) {
            float e = __expf(sc[tid*65 + s] - m);
            sc[tid*65 + s] = e; sum += e;
        }
        float inv = 1.0f / sum;
        for (int s = 0; s < 64; s++) sc[tid*65 + s] *= inv;
    }
    for (int e = tid; e < 4096; e += 256) sq[e] = g_v[(long)b * 4096 + e];
    __syncthreads();

    const float res = *res_scale;
    float outreg[16];
    {
        const int d = tid & 63;
        #pragma unroll
        for (int k = 0; k < 16; k++) {
            int g = (tid >> 6) + k*4;
            float s = 0.f;
            #pragma unroll 16
            for (int ss = 0; ss < 64; ss++) s += sc[g*65 + ss] * sq[ss*64 + d];
            outreg[k] = s + res * sst[g*64 + d];
        }
    }
    __syncthreads();
    {
        const int d = tid & 63;
        #pragma unroll
        for (int k = 0; k < 16; k++) sst[((tid >> 6) + k*4)*64 + d] = outreg[k];
    }
    __syncthreads();
    {   // fold Wout and write split M planes directly (no fp32 M, no splitM_k)
        const int c = tid;
        const float4* wp = reinterpret_cast<const float4*>(Wout + c*INNER_ + h*64);
        for (int g = 0; g < 64; g++) {
            const float4* op = reinterpret_cast<const float4*>(sst + g*64);
            float s = 0.f;
            #pragma unroll
            for (int d4 = 0; d4 < 16; d4++) {
                float4 w = wp[d4], o = op[d4];
                s += w.x*o.x + w.y*o.y + w.z*o.z + w.w*o.w;
            }
            long idx = ((long)b * DIM_ + c) * INNER_ + h*64 + g;
            split1(s, g_MHi[idx], g_MLo[idx]);
        }
    }
}

extern "C" void kernel_launch(void* const* d_in, const int* in_sizes, int n_in,
                              void* d_out, int out_size)
{
    const float* x         = (const float*)d_in[0];
    const float* Wfx       = (const float*)d_in[1];
    const float* bfx       = (const float*)d_in[2];
    const float* Wx        = (const float*)d_in[3];
    const float* bx        = (const float*)d_in[4];
    const float* Wslice    = (const float*)d_in[5];
    const float* bslice    = (const float*)d_in[6];
    const float* temp      = (const float*)d_in[7];
    const float* Wq        = (const float*)d_in[8];
    const float* Wk        = (const float*)d_in[9];
    const float* Wv        = (const float*)d_in[10];
    const float* res_scale = (const float*)d_in[11];
    const float* attn_scl  = (const float*)d_in[12];
    const float* Wout      = (const float*)d_in[13];
    const float* bout      = (const float*)d_in[14];
    float* out = (float*)d_out;

    bf16 *p_xHi, *p_xLo, *p_swHi, *p_swLo, *p_WcHi, *p_WcLo, *p_MHi, *p_MLo;
    float *p_lbias;
    cudaGetSymbolAddress((void**)&p_xHi, g_xHi);
    cudaGetSymbolAddress((void**)&p_xLo, g_xLo);
    cudaGetSymbolAddress((void**)&p_swHi, g_swHi);
    cudaGetSymbolAddress((void**)&p_swLo, g_swLo);
    cudaGetSymbolAddress((void**)&p_WcHi, g_WcombHi);
    cudaGetSymbolAddress((void**)&p_WcLo, g_WcombLo);
    cudaGetSymbolAddress((void**)&p_MHi, g_MHi);
    cudaGetSymbolAddress((void**)&p_MLo, g_MLo);
    cudaGetSymbolAddress((void**)&p_lbias, g_lbias);

    const int GEMM_SMEM = 2 * 4 * 128 * LDA * (int)sizeof(bf16);            // 81920
    const int P_SMEM    = 2 * (2*32*LDTA + 2*32*LDTB) * (int)sizeof(bf16);  // 53248
    cudaFuncSetAttribute(mma_gemm<true, true>,  cudaFuncAttributeMaxDynamicSharedMemorySize, GEMM_SMEM);
    cudaFuncSetAttribute(mma_gemm<false, false>, cudaFuncAttributeMaxDynamicSharedMemorySize, GEMM_SMEM);
    cudaFuncSetAttribute(pgemm_k, cudaFuncAttributeMaxDynamicSharedMemorySize, P_SMEM);
    cudaFuncSetAttribute(attn_k, cudaFuncAttributeMaxDynamicSharedMemorySize, 49408);

    splitX_k<<<(B_ * NPTS * DIM_) / 4 / 256, 256>>>(x);
    prep_k<<<512, 256>>>(Wx, Wslice, bx, bslice);

    // sw = softmax_G((x @ Wcomb^T + lbias)/temp) -> bf16 hi/lo planes
    mma_gemm<true, true><<<dim3(1024, 4, 1), 256, GEMM_SMEM>>>(
        p_xHi, p_xLo, p_WcHi, p_WcLo, p_lbias, temp,
        nullptr, p_swHi, p_swLo, INNER_, DIM_, 0, 0, 0);

    // P[b] = sw[b]^T @ X[b] (split-K=16 HMMA, snorm fused)
    pgemm_k<<<dim3(4, 4, B_ * PSPLITS), 256, P_SMEM>>>();

    st_k<<<dim3(BH_, 4), 256>>>(Wfx, bfx);
    kv_k<<<B_, 256>>>(Wk, Wv);
    attn_k<<<BH_, 256, 49408>>>(Wq, Wout, attn_scl, res_scale);

    // out = sw @ M[b]^T + bout
    mma_gemm<false, false><<<dim3(256, 2, B_), 256, GEMM_SMEM>>>(
        p_swHi, p_swLo, p_MHi, p_MLo, bout, nullptr,
        out, nullptr, nullptr, DIM_, INNER_,
        (long)NPTS * INNER_, (long)DIM_ * INNER_, (long)NPTS * DIM_);
}